// round 16
// baseline (speedup 1.0000x reference)
#include <cuda_runtime.h>
#include <cuda_bf16.h>
#include <cstdint>

#define VOCAB   8192
#define EMB     256
#define NROWS   16384
#define NCAND   16
#define NUNITS  1024        // 128 m-tiles x 8 v-chunks
#define VCH     1024        // codes per v-chunk
#define GCH     32          // codes per B chunk
#define CPU_    32          // chunks per unit (VCH/GCH)

// ---------------- global scratch ----------------
__device__ float g_e_half[VOCAB];
__device__ __align__(128) __nv_bfloat16 g_eb[(size_t)VOCAB * EMB];
__device__ int   g_cand[NROWS * NCAND];
__device__ float g_cval[NROWS * NCAND];

__device__ __forceinline__ uint32_t smem_u32(const void* p) {
    uint32_t a;
    asm("{ .reg .u64 t; cvta.to.shared.u64 t, %1; cvt.u32.u64 %0, t; }" : "=r"(a) : "l"(p));
    return a;
}
__device__ __forceinline__ void cp16(uint32_t dst, const void* src) {
    asm volatile("cp.async.cg.shared.global [%0], [%1], 16;" :: "r"(dst), "l"(src) : "memory");
}

#define MMA16816(c, a, bv0, bv1) \
    asm volatile("mma.sync.aligned.m16n8k16.row.col.f32.bf16.bf16.f32 " \
        "{%0,%1,%2,%3}, {%4,%5,%6,%7}, {%8,%9}, {%0,%1,%2,%3};" \
        : "+f"((c)[0]), "+f"((c)[1]), "+f"((c)[2]), "+f"((c)[3]) \
        : "r"((a)[0]), "r"((a)[1]), "r"((a)[2]), "r"((a)[3]), "r"(bv0), "r"(bv1))

#define LDMX4(r, addr) \
    asm volatile("ldmatrix.sync.aligned.m8n8.x4.shared.b16 {%0,%1,%2,%3}, [%4];" \
        : "=r"((r)[0]), "=r"((r)[1]), "=r"((r)[2]), "=r"((r)[3]) : "r"(addr))

__device__ __forceinline__ uint32_t pack_bf2(float a, float b) {
    __nv_bfloat162 h = __floats2bfloat162_rn(a, b);
    return *(uint32_t*)&h;
}

// ---------------- prep: cb->bf16 convert + e_half + ref zero ----------------
__global__ void vq_prep_kernel(const float* __restrict__ cb, float* __restrict__ ref_out) {
    const int gtid = blockIdx.x * blockDim.x + threadIdx.x;
    const int NE4 = VOCAB * EMB / 4;               // 524288; grid covers this
    if (gtid < NE4) {
        float4 v = ((const float4*)cb)[gtid];
        ((uint2*)g_eb)[gtid] = make_uint2(pack_bf2(v.x, v.y), pack_bf2(v.z, v.w));
    }
    const int warp = gtid >> 5;
    const int lane = threadIdx.x & 31;
    if (warp < VOCAB) {
        const float4* row = (const float4*)(cb + (size_t)warp * EMB);
        float4 a = row[lane];
        float4 b = row[lane + 32];
        float s = a.x*a.x + a.y*a.y + a.z*a.z + a.w*a.w
                + b.x*b.x + b.y*b.y + b.z*b.z + b.w*b.w;
        #pragma unroll
        for (int o = 16; o > 0; o >>= 1) s += __shfl_xor_sync(0xffffffffu, s, o);
        if (lane == 0) g_e_half[warp] = 0.5f * s;
    }
    if (gtid < VOCAB) ref_out[gtid] = 0.0f;
}

// ---------------- phase 1: persistent HMMA GEMM + per-unit top-2 -----------
#define BBUF    16384                   // bytes per B stage (32 codes x 512B)
#define SM_B    0                       // 4 x 16384 = 65536
#define SM_EH   65536                   // 32768
#define SM_A    98304                   // 128 rows x 512B = 65536
#define SMEM_GB 163840

#define TOP2(s_, c_, v1, i1, v2, i2) { float _t = (s_); \
    if (_t > (v2)) { if (_t > (v1)) { (v2)=(v1); (i2)=(i1); (v1)=_t; (i1)=(c_); } \
                     else          { (v2)=_t;  (i2)=(c_); } } }

#define INS4(s_, c_) { float _u = (s_); int _d = (c_); \
    if (_u > w3) { \
        if (_u > w1) { \
            if (_u > w0) { w3=w2;q3=q2; w2=w1;q2=q1; w1=w0;q1=q0; w0=_u;q0=_d; } \
            else         { w3=w2;q3=q2; w2=w1;q2=q1; w1=_u;q1=_d; } \
        } else { \
            if (_u > w2) { w3=w2;q3=q2; w2=_u;q2=_d; } \
            else         { w3=_u;q3=_d; } \
        } } }

// deferred epilogue: fold -0.5||e||^2, per-row top-2, reset buffer BUF
#define EPI(BUF, C0) { \
    _Pragma("unroll") \
    for (int nb_ = 0; nb_ < 4; ++nb_) { \
        const int ca_ = (C0) + nb_ * 8; \
        const float2 eh_ = *(const float2*)(sm + SM_EH + (size_t)ca_ * 4); \
        _Pragma("unroll") \
        for (int mb_ = 0; mb_ < 2; ++mb_) { \
            const int s0_ = mb_ * 2, s1_ = mb_ * 2 + 1; \
            TOP2(acc[BUF][mb_][nb_][0] - eh_.x, ca_,     tv1[s0_], ti1[s0_], tv2[s0_], ti2[s0_]); \
            TOP2(acc[BUF][mb_][nb_][1] - eh_.y, ca_ + 1, tv1[s0_], ti1[s0_], tv2[s0_], ti2[s0_]); \
            TOP2(acc[BUF][mb_][nb_][2] - eh_.x, ca_,     tv1[s1_], ti1[s1_], tv2[s1_], ti2[s1_]); \
            TOP2(acc[BUF][mb_][nb_][3] - eh_.y, ca_ + 1, tv1[s1_], ti1[s1_], tv2[s1_], ti2[s1_]); \
            acc[BUF][mb_][nb_][0] = 0.f; acc[BUF][mb_][nb_][1] = 0.f; \
            acc[BUF][mb_][nb_][2] = 0.f; acc[BUF][mb_][nb_][3] = 0.f; \
        } \
    } \
}

__global__ void __launch_bounds__(128, 1) vq_gemm_kernel(const float* __restrict__ z) {
    extern __shared__ char sm[];
    const uint32_t sb = smem_u32(sm);
    const int tid  = threadIdx.x;
    const int lane = tid & 31;
    const int warp = tid >> 5;

    // contiguous unit range for this CTA
    const int u0 = (NUNITS * blockIdx.x) / gridDim.x;
    const int u1 = (NUNITS * (blockIdx.x + 1)) / gridDim.x;
    const int T  = (u1 - u0) * CPU_;    // flat chunk count (multiple of 32)

    // e_half table (once)
    for (int i = tid; i < VOCAB; i += 128)
        *(float*)(sm + SM_EH + i * 4) = g_e_half[i];
    __syncthreads();

    // prime B prefetch for flat chunks 0,1
    #pragma unroll
    for (int p = 0; p < 2; ++p) {
        const int up = u0 + (p >> 5);
        const size_t code0 = (size_t)((up & 7) * VCH + (p & 31) * GCH);
        const char* src = (const char*)g_eb + code0 * 512;
        uint32_t dstb = sb + SM_B + (uint32_t)(p & 3) * BBUF;
        #pragma unroll
        for (int j = 0; j < 8; ++j) {
            int uu = tid + j * 128;
            int n = uu >> 5, g = uu & 31;
            cp16(dstb + n * 512 + ((g ^ (n & 7)) << 4), src + (size_t)uu * 16);
        }
        asm volatile("cp.async.commit_group;" ::: "memory");
    }

    uint32_t A[2][16][4];
    float acc[2][2][4][4];              // [buf][mb][nb][q]
    #pragma unroll
    for (int bf = 0; bf < 2; ++bf)
        #pragma unroll
        for (int mb = 0; mb < 2; ++mb)
            #pragma unroll
            for (int nb = 0; nb < 4; ++nb)
                #pragma unroll
                for (int q = 0; q < 4; ++q) acc[bf][mb][nb][q] = 0.f;

    float tv1[4], tv2[4];
    int   ti1[4], ti2[4];

    const int nbase = ((lane >> 4) & 1) * 8 + (lane & 7);
    const uint32_t brow0 = (uint32_t)nbase * 512;
    const uint32_t brow1 = (uint32_t)(nbase + 16) * 512;
    const int gb = (lane >> 3) & 1;
    const int sw = lane & 7;

    int cur_m = -1;
    int c0p = 0;                        // epilogue base of the pending chunk

    for (int tt = 0; tt < T; tt += 2) {
        const int u = u0 + (tt >> 5);
        const int m = u >> 3;
        const int v = u & 7;

        if ((tt & 31) == 0) {
            if (m != cur_m) {
                // ---- (re)load A tile: LDG fp32 -> bf16 STS (swizzled) ----
                __syncthreads();   // prior readers of SM_A done; converge
                const float* srcA = z + (size_t)m * 128 * 256;
                #pragma unroll
                for (int j = 0; j < 32; ++j) {        // 4096 granules: full 128 rows
                    int uu = tid + j * 128;           // granule 0..4095
                    int n = uu >> 5, g = uu & 31;
                    const float4 f0 = *(const float4*)(srcA + n * 256 + g * 8);
                    const float4 f1 = *(const float4*)(srcA + n * 256 + g * 8 + 4);
                    uint4 val;
                    val.x = pack_bf2(f0.x, f0.y);
                    val.y = pack_bf2(f0.z, f0.w);
                    val.z = pack_bf2(f1.x, f1.y);
                    val.w = pack_bf2(f1.z, f1.w);
                    *(uint4*)(sm + SM_A + n * 512 + ((g ^ (n & 7)) << 4)) = val;
                }
                __syncthreads();
                #pragma unroll
                for (int mb = 0; mb < 2; ++mb) {
                    const int r = warp * 32 + mb * 16 + (lane & 8) + (lane & 7);
                    #pragma unroll
                    for (int kb = 0; kb < 16; ++kb) {
                        uint32_t addr = sb + SM_A + r * 512 + (((2 * kb + (lane >> 4)) ^ (lane & 7)) << 4);
                        LDMX4(A[mb][kb], addr);
                    }
                }
                cur_m = m;
            }
            // reset per-unit top-2
            #pragma unroll
            for (int s = 0; s < 4; ++s) { tv1[s] = -3.4e38f; tv2[s] = -3.4e38f; ti1[s] = 0; ti2[s] = 0; }
        }

        // wait for chunks tt, tt+1
        asm volatile("cp.async.wait_group 0;" ::: "memory");
        __syncthreads();

        // prefetch chunks tt+2, tt+3 into the two free buffers
        #pragma unroll
        for (int q = 0; q < 2; ++q) {
            const int p = tt + 2 + q;
            if (p < T) {
                const int up = u0 + (p >> 5);
                const size_t code0 = (size_t)((up & 7) * VCH + (p & 31) * GCH);
                const char* src = (const char*)g_eb + code0 * 512;
                uint32_t dstb = sb + SM_B + (uint32_t)(p & 3) * BBUF;
                #pragma unroll
                for (int j = 0; j < 8; ++j) {
                    int uu = tid + j * 128;
                    int n = uu >> 5, g = uu & 31;
                    cp16(dstb + n * 512 + ((g ^ (n & 7)) << 4), src + (size_t)uu * 16);
                }
                asm volatile("cp.async.commit_group;" ::: "memory");
            }
        }

        // process the two ready chunks; epilogue of chunk t-1 deferred
        // behind chunk t's MMA stream (buffer h is compile-time)
        #pragma unroll
        for (int h = 0; h < 2; ++h) {
            const int t  = tt + h;
            const int cc = t & 31;
            const uint32_t bb = sb + SM_B + (uint32_t)(t & 3) * BBUF;
            const int c0 = v * VCH + cc * GCH + 2 * (lane & 3);

            #pragma unroll
            for (int kb = 0; kb < 16; ++kb) {
                uint32_t b0r[4], b1r[4];
                const uint32_t go = (uint32_t)(((2 * kb + gb) ^ sw) << 4);
                LDMX4(b0r, bb + brow0 + go);   // n-blocks 0,1
                LDMX4(b1r, bb + brow1 + go);   // n-blocks 2,3
                #pragma unroll
                for (int mb = 0; mb < 2; ++mb) {
                    MMA16816(acc[h][mb][0], A[mb][kb], b0r[0], b0r[1]);
                    MMA16816(acc[h][mb][1], A[mb][kb], b0r[2], b0r[3]);
                    MMA16816(acc[h][mb][2], A[mb][kb], b1r[0], b1r[1]);
                    MMA16816(acc[h][mb][3], A[mb][kb], b1r[2], b1r[3]);
                }
            }

            // deferred epilogue of the previous chunk (same unit only)
            if (!(h == 0 && (tt & 31) == 0)) {
                EPI(h ^ 1, c0p);
            }
            c0p = c0;
        }

        if ((tt & 31) == 30) {
            // flush pending epilogue of chunk tt+1 (buffer 1)
            EPI(1, c0p);
            // ---- unit done: quad-merge to per-row top-2, write g_cand/g_cval ----
            #pragma unroll
            for (int slot = 0; slot < 4; ++slot) {
                float w0 = tv1[slot], w1 = tv2[slot], w2 = -3.4e38f, w3 = -3.4e38f;
                int   q0 = ti1[slot], q1 = ti2[slot], q2 = 0, q3 = 0;
                #pragma unroll
                for (int d = 1; d <= 2; d <<= 1) {
                    float o0 = __shfl_xor_sync(0xffffffffu, w0, d);
                    float o1 = __shfl_xor_sync(0xffffffffu, w1, d);
                    float o2 = __shfl_xor_sync(0xffffffffu, w2, d);
                    float o3 = __shfl_xor_sync(0xffffffffu, w3, d);
                    int   p0 = __shfl_xor_sync(0xffffffffu, q0, d);
                    int   p1 = __shfl_xor_sync(0xffffffffu, q1, d);
                    int   p2 = __shfl_xor_sync(0xffffffffu, q2, d);
                    int   p3 = __shfl_xor_sync(0xffffffffu, q3, d);
                    INS4(o0, p0); INS4(o1, p1); INS4(o2, p2); INS4(o3, p3);
                }
                if ((lane & 3) == 0) {
                    const int row = m * 128 + warp * 32 + slot * 8 + (lane >> 2);
                    g_cand[row * NCAND + v * 2 + 0] = q0;
                    g_cand[row * NCAND + v * 2 + 1] = q1;
                    g_cval[row * NCAND + v * 2 + 0] = w0;
                    g_cval[row * NCAND + v * 2 + 1] = w1;
                }
            }
        }
    }
}

// ---------------- phase 2: eligible-subset exact rescore + outputs ---------
#define ERRB 0.4f   // two-sided bf16-score error bound (7.7 sigma one-sided)

__global__ void __launch_bounds__(256) vq_rescore_kernel(
    const float* __restrict__ z, const float* __restrict__ cb,
    float* __restrict__ tok, float* __restrict__ zq, float* __restrict__ ref) {
    const int warp = threadIdx.x >> 5, lane = threadIdx.x & 31;
    const int row  = blockIdx.x * 8 + warp;

    // approx (val, idx) per lane (lanes 0..15 hold candidates; indices distinct)
    float av = -3.4e38f;
    int   ac = 0x7fffffff;
    if (lane < NCAND) {
        av = g_cval[row * NCAND + lane];
        ac = g_cand[row * NCAND + lane];
    }
    // warp top-1 (lowest index on value tie)
    float bv = av; int bidx = ac;
    #pragma unroll
    for (int o = 16; o > 0; o >>= 1) {
        float ov = __shfl_xor_sync(0xffffffffu, bv, o);
        int   oi = __shfl_xor_sync(0xffffffffu, bidx, o);
        if (ov > bv || (ov == bv && oi < bidx)) { bv = ov; bidx = oi; }
    }

    // eligible set: only candidates within ERRB of the approx best can win
    const unsigned elig = __ballot_sync(0xffffffffu, lane < NCAND && av >= bv - ERRB);

    int bi;
    if (__popc(elig) == 1) {
        bi = bidx;                       // certain: exact order cannot flip
    } else {
        const float4* zr = (const float4*)(z + (size_t)row * EMB);
        const float4 z0 = zr[lane * 2], z1 = zr[lane * 2 + 1];
        float best = -3.4e38f;
        bi = 0x7fffffff;
        unsigned msk = elig;
        while (msk) {
            const int l = __ffs(msk) - 1; msk &= msk - 1;
            const int c = __shfl_sync(0xffffffffu, ac, l);
            const float4* er = (const float4*)(cb + (size_t)c * EMB);
            const float4 e0 = er[lane * 2], e1 = er[lane * 2 + 1];
            float d = z0.x*e0.x + z0.y*e0.y + z0.z*e0.z + z0.w*e0.w
                    + z1.x*e1.x + z1.y*e1.y + z1.z*e1.z + z1.w*e1.w;
            #pragma unroll
            for (int o = 16; o > 0; o >>= 1) d += __shfl_xor_sync(0xffffffffu, d, o);
            const float s = d - g_e_half[c];
            if (s > best || (s == best && c < bi)) { best = s; bi = c; }
        }
    }

    tok[row] = (float)bi;
    if (lane == 0) atomicAdd(&ref[bi], 1.0f);
    const float4* eb = (const float4*)(cb + (size_t)bi * EMB);
    float4* o = (float4*)(zq + (size_t)row * EMB);
    o[lane * 2]     = eb[lane * 2];
    o[lane * 2 + 1] = eb[lane * 2 + 1];
}

// ---------------- launch ----------------------------------------------------
extern "C" void kernel_launch(void* const* d_in, const int* in_sizes, int n_in,
                              void* d_out, int out_size) {
    const float* z;
    const float* cb;
    if (in_sizes[0] == NROWS * EMB) { z = (const float*)d_in[0]; cb = (const float*)d_in[1]; }
    else                            { z = (const float*)d_in[1]; cb = (const float*)d_in[0]; }

    float* out = (float*)d_out;
    float* tok = out;
    float* zq  = out + NROWS;
    float* ref = out + NROWS + (size_t)NROWS * EMB;

    int dev = 0, nsm = 0;
    cudaGetDevice(&dev);
    if (cudaDeviceGetAttribute(&nsm, cudaDevAttrMultiProcessorCount, dev) != cudaSuccess || nsm <= 0)
        nsm = 148;
    if (nsm > NUNITS) nsm = NUNITS;

    cudaFuncSetAttribute(vq_gemm_kernel, cudaFuncAttributeMaxDynamicSharedMemorySize, SMEM_GB);

    vq_prep_kernel<<<(VOCAB * EMB / 4) / 256, 256>>>(cb, ref);
    vq_gemm_kernel<<<nsm, 128, SMEM_GB>>>(z);
    vq_rescore_kernel<<<NROWS / 8, 256>>>(z, cb, tok, zq, ref);
}

// round 17
// speedup vs baseline: 1.1597x; 1.1597x over previous
#include <cuda_runtime.h>
#include <cuda_bf16.h>
#include <cstdint>

#define VOCAB   8192
#define EMB     256
#define NROWS   16384
#define NCAND   16
#define NUNITS  1024        // 128 m-tiles x 8 v-chunks
#define VCH     1024        // codes per v-chunk
#define GCH     32          // codes per B chunk
#define CPU_    32          // chunks per unit (VCH/GCH)

// ---------------- global scratch ----------------
__device__ float g_e_half[VOCAB];
__device__ __align__(128) __nv_bfloat16 g_eb[(size_t)VOCAB * EMB];
__device__ __align__(128) uint8_t g_zbs[(size_t)NROWS * 512];   // bf16, pre-swizzled rows
__device__ int   g_cand[NROWS * NCAND];
__device__ float g_cval[NROWS * NCAND];

__device__ __forceinline__ uint32_t smem_u32(const void* p) {
    uint32_t a;
    asm("{ .reg .u64 t; cvta.to.shared.u64 t, %1; cvt.u32.u64 %0, t; }" : "=r"(a) : "l"(p));
    return a;
}
__device__ __forceinline__ void cp16(uint32_t dst, const void* src) {
    asm volatile("cp.async.cg.shared.global [%0], [%1], 16;" :: "r"(dst), "l"(src) : "memory");
}

#define MMA16816(c, a, bv0, bv1) \
    asm volatile("mma.sync.aligned.m16n8k16.row.col.f32.bf16.bf16.f32 " \
        "{%0,%1,%2,%3}, {%4,%5,%6,%7}, {%8,%9}, {%0,%1,%2,%3};" \
        : "+f"((c)[0]), "+f"((c)[1]), "+f"((c)[2]), "+f"((c)[3]) \
        : "r"((a)[0]), "r"((a)[1]), "r"((a)[2]), "r"((a)[3]), "r"(bv0), "r"(bv1))

#define LDMX4(r, addr) \
    asm volatile("ldmatrix.sync.aligned.m8n8.x4.shared.b16 {%0,%1,%2,%3}, [%4];" \
        : "=r"((r)[0]), "=r"((r)[1]), "=r"((r)[2]), "=r"((r)[3]) : "r"(addr))

__device__ __forceinline__ uint32_t pack_bf2(float a, float b) {
    __nv_bfloat162 h = __floats2bfloat162_rn(a, b);
    return *(uint32_t*)&h;
}

// ------ prep: cb->bf16 + z->bf16 (pre-swizzled) + e_half + ref zero --------
__global__ void vq_prep_kernel(const float* __restrict__ z, const float* __restrict__ cb,
                               float* __restrict__ ref_out) {
    const int gtid = blockIdx.x * blockDim.x + threadIdx.x;
    const int NE4 = VOCAB * EMB / 4;               // 524288; grid covers this
    if (gtid < NE4) {
        float4 v = ((const float4*)cb)[gtid];
        ((uint2*)g_eb)[gtid] = make_uint2(pack_bf2(v.x, v.y), pack_bf2(v.z, v.w));
    }
    // z: one 16B bf16 granule per thread, stored pre-swizzled
    {
        const int r = gtid >> 5;                   // row 0..16383 (gtid < 524288)
        const int g = gtid & 31;                   // granule within row
        const float* src = z + (size_t)r * EMB + g * 8;
        const float4 f0 = *(const float4*)(src);
        const float4 f1 = *(const float4*)(src + 4);
        uint4 val;
        val.x = pack_bf2(f0.x, f0.y);
        val.y = pack_bf2(f0.z, f0.w);
        val.z = pack_bf2(f1.x, f1.y);
        val.w = pack_bf2(f1.z, f1.w);
        *(uint4*)(g_zbs + (size_t)r * 512 + ((g ^ (r & 7)) << 4)) = val;
    }
    const int warp = gtid >> 5;
    const int lane = threadIdx.x & 31;
    if (warp < VOCAB) {
        const float4* row = (const float4*)(cb + (size_t)warp * EMB);
        float4 a = row[lane];
        float4 b = row[lane + 32];
        float s = a.x*a.x + a.y*a.y + a.z*a.z + a.w*a.w
                + b.x*b.x + b.y*b.y + b.z*b.z + b.w*b.w;
        #pragma unroll
        for (int o = 16; o > 0; o >>= 1) s += __shfl_xor_sync(0xffffffffu, s, o);
        if (lane == 0) g_e_half[warp] = 0.5f * s;
    }
    if (gtid < VOCAB) ref_out[gtid] = 0.0f;
}

// ---------------- phase 1: persistent HMMA GEMM + per-unit top-2 -----------
#define BBUF    16384                   // bytes per B stage (32 codes x 512B)
#define SM_B    0                       // 4 x 16384 = 65536
#define SM_EH   65536                   // 32768
#define SM_A    98304                   // 128 rows x 512B = 65536
#define SMEM_GB 163840

#define TOP2(s_, c_, v1, i1, v2, i2) { float _t = (s_); \
    if (_t > (v2)) { if (_t > (v1)) { (v2)=(v1); (i2)=(i1); (v1)=_t; (i1)=(c_); } \
                     else          { (v2)=_t;  (i2)=(c_); } } }

#define INS4(s_, c_) { float _u = (s_); int _d = (c_); \
    if (_u > w3) { \
        if (_u > w1) { \
            if (_u > w0) { w3=w2;q3=q2; w2=w1;q2=q1; w1=w0;q1=q0; w0=_u;q0=_d; } \
            else         { w3=w2;q3=q2; w2=w1;q2=q1; w1=_u;q1=_d; } \
        } else { \
            if (_u > w2) { w3=w2;q3=q2; w2=_u;q2=_d; } \
            else         { w3=_u;q3=_d; } \
        } } }

__global__ void __launch_bounds__(128, 1) vq_gemm_kernel() {
    extern __shared__ char sm[];
    const uint32_t sb = smem_u32(sm);
    const int tid  = threadIdx.x;
    const int lane = tid & 31;
    const int warp = tid >> 5;

    // contiguous unit range for this CTA
    const int u0 = (NUNITS * blockIdx.x) / gridDim.x;
    const int u1 = (NUNITS * (blockIdx.x + 1)) / gridDim.x;
    const int T  = (u1 - u0) * CPU_;    // flat chunk count (multiple of 32)

    // e_half table (once)
    for (int i = tid; i < VOCAB; i += 128)
        *(float*)(sm + SM_EH + i * 4) = g_e_half[i];
    __syncthreads();

    // prime B prefetch for flat chunks 0,1
    #pragma unroll
    for (int p = 0; p < 2; ++p) {
        const int up = u0 + (p >> 5);
        const size_t code0 = (size_t)((up & 7) * VCH + (p & 31) * GCH);
        const char* src = (const char*)g_eb + code0 * 512;
        uint32_t dstb = sb + SM_B + (uint32_t)(p & 3) * BBUF;
        #pragma unroll
        for (int j = 0; j < 8; ++j) {
            int uu = tid + j * 128;
            int n = uu >> 5, g = uu & 31;
            cp16(dstb + n * 512 + ((g ^ (n & 7)) << 4), src + (size_t)uu * 16);
        }
        asm volatile("cp.async.commit_group;" ::: "memory");
    }

    uint32_t A[2][16][4];
    float acc[2][4][4];
    #pragma unroll
    for (int mb = 0; mb < 2; ++mb)
        #pragma unroll
        for (int nb = 0; nb < 4; ++nb)
            #pragma unroll
            for (int q = 0; q < 4; ++q) acc[mb][nb][q] = 0.f;

    float tv1[4], tv2[4];
    int   ti1[4], ti2[4];

    const int nbase = ((lane >> 4) & 1) * 8 + (lane & 7);
    const uint32_t brow0 = (uint32_t)nbase * 512;
    const uint32_t brow1 = (uint32_t)(nbase + 16) * 512;
    const int gb = (lane >> 3) & 1;
    const int sw = lane & 7;

    int cur_m = -1;

    for (int tt = 0; tt < T; tt += 2) {
        const int u = u0 + (tt >> 5);
        const int m = u >> 3;
        const int v = u & 7;

        if ((tt & 31) == 0) {
            if (m != cur_m) {
                // ---- (re)load A tile: identity cp.async copy (pre-swizzled bf16) ----
                __syncthreads();   // prior readers of SM_A done; converge
                const char* srcA = (const char*)g_zbs + (size_t)m * 128 * 512;
                #pragma unroll
                for (int j = 0; j < 32; ++j) {
                    int uu = tid + j * 128;           // granule 0..4095
                    cp16(sb + SM_A + (uint32_t)uu * 16, srcA + (size_t)uu * 16);
                }
                asm volatile("cp.async.commit_group;" ::: "memory");
                asm volatile("cp.async.wait_group 0;" ::: "memory");  // A (+pending B: fine)
                __syncthreads();
                #pragma unroll
                for (int mb = 0; mb < 2; ++mb) {
                    const int r = warp * 32 + mb * 16 + (lane & 8) + (lane & 7);
                    #pragma unroll
                    for (int kb = 0; kb < 16; ++kb) {
                        uint32_t addr = sb + SM_A + r * 512 + (((2 * kb + (lane >> 4)) ^ (lane & 7)) << 4);
                        LDMX4(A[mb][kb], addr);
                    }
                }
                cur_m = m;
            }
            // reset per-unit top-2
            #pragma unroll
            for (int s = 0; s < 4; ++s) { tv1[s] = -3.4e38f; tv2[s] = -3.4e38f; ti1[s] = 0; ti2[s] = 0; }
        }

        // wait for chunks tt, tt+1
        asm volatile("cp.async.wait_group 0;" ::: "memory");
        __syncthreads();

        // prefetch chunks tt+2, tt+3 into the two free buffers
        #pragma unroll
        for (int q = 0; q < 2; ++q) {
            const int p = tt + 2 + q;
            if (p < T) {
                const int up = u0 + (p >> 5);
                const size_t code0 = (size_t)((up & 7) * VCH + (p & 31) * GCH);
                const char* src = (const char*)g_eb + code0 * 512;
                uint32_t dstb = sb + SM_B + (uint32_t)(p & 3) * BBUF;
                #pragma unroll
                for (int j = 0; j < 8; ++j) {
                    int uu = tid + j * 128;
                    int n = uu >> 5, g = uu & 31;
                    cp16(dstb + n * 512 + ((g ^ (n & 7)) << 4), src + (size_t)uu * 16);
                }
                asm volatile("cp.async.commit_group;" ::: "memory");
            }
        }

        // process the two ready chunks
        #pragma unroll
        for (int h = 0; h < 2; ++h) {
            const int t  = tt + h;
            const int cc = t & 31;
            const uint32_t bb = sb + SM_B + (uint32_t)(t & 3) * BBUF;

            #pragma unroll
            for (int kb = 0; kb < 16; ++kb) {
                uint32_t b0r[4], b1r[4];
                const uint32_t go = (uint32_t)(((2 * kb + gb) ^ sw) << 4);
                LDMX4(b0r, bb + brow0 + go);   // n-blocks 0,1
                LDMX4(b1r, bb + brow1 + go);   // n-blocks 2,3
                #pragma unroll
                for (int mb = 0; mb < 2; ++mb) {
                    MMA16816(acc[mb][0], A[mb][kb], b0r[0], b0r[1]);
                    MMA16816(acc[mb][1], A[mb][kb], b0r[2], b0r[3]);
                    MMA16816(acc[mb][2], A[mb][kb], b1r[0], b1r[1]);
                    MMA16816(acc[mb][3], A[mb][kb], b1r[2], b1r[3]);
                }
            }

            // epilogue: fold -0.5||e||^2, per-row top-2, reset acc
            const int c0 = v * VCH + cc * GCH + 2 * (lane & 3);
            #pragma unroll
            for (int nb = 0; nb < 4; ++nb) {
                const int ca = c0 + nb * 8;
                const float2 eh = *(const float2*)(sm + SM_EH + (size_t)ca * 4);
                #pragma unroll
                for (int mb = 0; mb < 2; ++mb) {
                    const int s0 = mb * 2, s1 = mb * 2 + 1;
                    TOP2(acc[mb][nb][0] - eh.x, ca,     tv1[s0], ti1[s0], tv2[s0], ti2[s0]);
                    TOP2(acc[mb][nb][1] - eh.y, ca + 1, tv1[s0], ti1[s0], tv2[s0], ti2[s0]);
                    TOP2(acc[mb][nb][2] - eh.x, ca,     tv1[s1], ti1[s1], tv2[s1], ti2[s1]);
                    TOP2(acc[mb][nb][3] - eh.y, ca + 1, tv1[s1], ti1[s1], tv2[s1], ti2[s1]);
                    acc[mb][nb][0] = 0.f; acc[mb][nb][1] = 0.f;
                    acc[mb][nb][2] = 0.f; acc[mb][nb][3] = 0.f;
                }
            }
        }

        if ((tt & 31) == 30) {
            // ---- unit done: quad-merge to per-row top-2, write g_cand/g_cval ----
            #pragma unroll
            for (int slot = 0; slot < 4; ++slot) {
                float w0 = tv1[slot], w1 = tv2[slot], w2 = -3.4e38f, w3 = -3.4e38f;
                int   q0 = ti1[slot], q1 = ti2[slot], q2 = 0, q3 = 0;
                #pragma unroll
                for (int d = 1; d <= 2; d <<= 1) {
                    float o0 = __shfl_xor_sync(0xffffffffu, w0, d);
                    float o1 = __shfl_xor_sync(0xffffffffu, w1, d);
                    float o2 = __shfl_xor_sync(0xffffffffu, w2, d);
                    float o3 = __shfl_xor_sync(0xffffffffu, w3, d);
                    int   p0 = __shfl_xor_sync(0xffffffffu, q0, d);
                    int   p1 = __shfl_xor_sync(0xffffffffu, q1, d);
                    int   p2 = __shfl_xor_sync(0xffffffffu, q2, d);
                    int   p3 = __shfl_xor_sync(0xffffffffu, q3, d);
                    INS4(o0, p0); INS4(o1, p1); INS4(o2, p2); INS4(o3, p3);
                }
                if ((lane & 3) == 0) {
                    const int row = m * 128 + warp * 32 + slot * 8 + (lane >> 2);
                    g_cand[row * NCAND + v * 2 + 0] = q0;
                    g_cand[row * NCAND + v * 2 + 1] = q1;
                    g_cval[row * NCAND + v * 2 + 0] = w0;
                    g_cval[row * NCAND + v * 2 + 1] = w1;
                }
            }
        }
    }
}

// ---------------- phase 2: eligible-subset exact rescore + outputs ---------
#define ERRB 0.4f   // two-sided bf16-score error bound (7.7 sigma one-sided)

__global__ void __launch_bounds__(256) vq_rescore_kernel(
    const float* __restrict__ z, const float* __restrict__ cb,
    float* __restrict__ tok, float* __restrict__ zq, float* __restrict__ ref) {
    const int warp = threadIdx.x >> 5, lane = threadIdx.x & 31;
    const int row  = blockIdx.x * 8 + warp;

    // approx (val, idx) per lane (lanes 0..15 hold candidates; indices distinct)
    float av = -3.4e38f;
    int   ac = 0x7fffffff;
    if (lane < NCAND) {
        av = g_cval[row * NCAND + lane];
        ac = g_cand[row * NCAND + lane];
    }
    // warp top-1 (lowest index on value tie)
    float bv = av; int bidx = ac;
    #pragma unroll
    for (int o = 16; o > 0; o >>= 1) {
        float ov = __shfl_xor_sync(0xffffffffu, bv, o);
        int   oi = __shfl_xor_sync(0xffffffffu, bidx, o);
        if (ov > bv || (ov == bv && oi < bidx)) { bv = ov; bidx = oi; }
    }

    // eligible set: only candidates within ERRB of the approx best can win
    const unsigned elig = __ballot_sync(0xffffffffu, lane < NCAND && av >= bv - ERRB);

    int bi;
    if (__popc(elig) == 1) {
        bi = bidx;                       // certain: exact order cannot flip
    } else {
        const float4* zr = (const float4*)(z + (size_t)row * EMB);
        const float4 z0 = zr[lane * 2], z1 = zr[lane * 2 + 1];
        float best = -3.4e38f;
        bi = 0x7fffffff;
        unsigned msk = elig;
        while (msk) {
            const int l = __ffs(msk) - 1; msk &= msk - 1;
            const int c = __shfl_sync(0xffffffffu, ac, l);
            const float4* er = (const float4*)(cb + (size_t)c * EMB);
            const float4 e0 = er[lane * 2], e1 = er[lane * 2 + 1];
            float d = z0.x*e0.x + z0.y*e0.y + z0.z*e0.z + z0.w*e0.w
                    + z1.x*e1.x + z1.y*e1.y + z1.z*e1.z + z1.w*e1.w;
            #pragma unroll
            for (int o = 16; o > 0; o >>= 1) d += __shfl_xor_sync(0xffffffffu, d, o);
            const float s = d - g_e_half[c];
            if (s > best || (s == best && c < bi)) { best = s; bi = c; }
        }
    }

    tok[row] = (float)bi;
    if (lane == 0) atomicAdd(&ref[bi], 1.0f);
    const float4* eb = (const float4*)(cb + (size_t)bi * EMB);
    float4* o = (float4*)(zq + (size_t)row * EMB);
    o[lane * 2]     = eb[lane * 2];
    o[lane * 2 + 1] = eb[lane * 2 + 1];
}

// ---------------- launch ----------------------------------------------------
extern "C" void kernel_launch(void* const* d_in, const int* in_sizes, int n_in,
                              void* d_out, int out_size) {
    const float* z;
    const float* cb;
    if (in_sizes[0] == NROWS * EMB) { z = (const float*)d_in[0]; cb = (const float*)d_in[1]; }
    else                            { z = (const float*)d_in[1]; cb = (const float*)d_in[0]; }

    float* out = (float*)d_out;
    float* tok = out;
    float* zq  = out + NROWS;
    float* ref = out + NROWS + (size_t)NROWS * EMB;

    int dev = 0, nsm = 0;
    cudaGetDevice(&dev);
    if (cudaDeviceGetAttribute(&nsm, cudaDevAttrMultiProcessorCount, dev) != cudaSuccess || nsm <= 0)
        nsm = 148;
    if (nsm > NUNITS) nsm = NUNITS;

    cudaFuncSetAttribute(vq_gemm_kernel, cudaFuncAttributeMaxDynamicSharedMemorySize, SMEM_GB);

    vq_prep_kernel<<<(VOCAB * EMB / 4) / 256, 256>>>(z, cb, ref);
    vq_gemm_kernel<<<nsm, 128, SMEM_GB>>>();
    vq_rescore_kernel<<<NROWS / 8, 256>>>(z, cb, tok, zq, ref);
}